// round 2
// baseline (speedup 1.0000x reference)
#include <cuda_runtime.h>
#include <math.h>

#define NN    4096
#define INS   256
#define OUTS  64
#define MECHS 4
#define LEAKF 0.2f
#define ADJW  (NN/32)     // 128 words per row

// ---------------- scratch (device globals; no allocation allowed) ------------
__device__ float    g_pool_part[32][256];
__device__ float    g_pooled[256];                 // mean-pooled x
__device__ float    g_gb[512];                     // gamma[256], beta[256]
__device__ float    g_h[MECHS * NN * OUTS];        // FiLM'd features, 4 MB
__device__ float    g_esrc[MECHS * NN];
__device__ float    g_edst[MECHS * NN];
__device__ unsigned g_adjbits[NN * ADJW];          // packed adjacency, 2 MB

// ---------------- 1) column-mean of x (two-stage, deterministic) -------------
__global__ void pool_partial_k(const float* __restrict__ x) {
    int t = threadIdx.x, b = blockIdx.x;
    int r0 = b * 128;
    float acc = 0.f;
    for (int r = 0; r < 128; ++r) acc += x[(r0 + r) * INS + t];
    g_pool_part[b][t] = acc;
}

__global__ void pool_final_k() {
    int t = threadIdx.x;
    float acc = 0.f;
    for (int b = 0; b < 32; ++b) acc += g_pool_part[b][t];
    g_pooled[t] = acc * (1.0f / NN);
}

// ---------------- 2) conditioner: gb = pooled @ Wc + bc ----------------------
__global__ void cond_k(const float* __restrict__ Wc, const float* __restrict__ bc) {
    __shared__ float ps[256];
    int t = threadIdx.x;
    ps[t] = g_pooled[t];
    __syncthreads();
    int c = blockIdx.x * 256 + t;
    float acc = bc[c];
    for (int i = 0; i < INS; ++i) acc = fmaf(ps[i], Wc[i * 512 + c], acc);
    g_gb[c] = acc;
}

// ---------------- 3) pack adjacency into bitmask -----------------------------
// One warp packs one 32-bit word; 8 warps per block; 65536 blocks total.
__global__ void pack_adj_k(const int* __restrict__ adj) {
    int w    = blockIdx.x * 8 + (threadIdx.x >> 5);
    int lane = threadIdx.x & 31;
    int row  = w >> 7;
    int wc   = w & 127;
    int v = adj[row * NN + wc * 32 + lane];
    unsigned mask = __ballot_sync(0xffffffffu, v > 0);
    if (lane == 0) g_adjbits[w] = mask;
}

// ---------------- 4) h = FiLM(x @ W[m])  (tiled SGEMM, 64x64 tiles) ----------
__global__ void hgemm_k(const float* __restrict__ x, const float* __restrict__ W) {
    __shared__ float xs[64][20];   // row stride 20 floats (80B, 16B-aligned)
    __shared__ float ws[16][64];

    int m  = blockIdx.x;
    int rb = blockIdx.y * 64;
    int tx = threadIdx.x, ty = threadIdx.y;
    int t  = ty * 16 + tx;

    float acc[4][4] = {};
    const float* Wm = W + m * INS * OUTS;

    for (int k0 = 0; k0 < INS; k0 += 16) {
        {   // load x tile  [64 x 16]
            int r = t >> 2, kq = (t & 3) * 4;
            float4 v = *(const float4*)&x[(rb + r) * INS + k0 + kq];
            *(float4*)&xs[r][kq] = v;
        }
        {   // load W tile  [16 x 64]
            int kk = t >> 4, oq = (t & 15) * 4;
            *(float4*)&ws[kk][oq] = *(const float4*)&Wm[(k0 + kk) * OUTS + oq];
        }
        __syncthreads();
        #pragma unroll
        for (int k = 0; k < 16; ++k) {
            float a[4];
            #pragma unroll
            for (int i = 0; i < 4; ++i) a[i] = xs[ty * 4 + i][k];
            float4 b4 = *(const float4*)&ws[k][tx * 4];
            float b[4] = {b4.x, b4.y, b4.z, b4.w};
            #pragma unroll
            for (int i = 0; i < 4; ++i)
                #pragma unroll
                for (int j = 0; j < 4; ++j)
                    acc[i][j] = fmaf(a[i], b[j], acc[i][j]);
        }
        __syncthreads();
    }

    // FiLM + store
    int oc = tx * 4;
    float4 gm = *(const float4*)&g_gb[m * 64 + oc];
    float4 bt = *(const float4*)&g_gb[256 + m * 64 + oc];
    #pragma unroll
    for (int i = 0; i < 4; ++i) {
        int row = rb + ty * 4 + i;
        float4 hv;
        hv.x = fmaf(gm.x, acc[i][0], bt.x);
        hv.y = fmaf(gm.y, acc[i][1], bt.y);
        hv.z = fmaf(gm.z, acc[i][2], bt.z);
        hv.w = fmaf(gm.w, acc[i][3], bt.w);
        *(float4*)&g_h[(m * NN + row) * OUTS + oc] = hv;
    }
}

// ---------------- 5) e_src / e_dst (one warp per (m,n)) ----------------------
__global__ void esd_k(const float* __restrict__ a1, const float* __restrict__ a2) {
    int wg   = blockIdx.x * 8 + (threadIdx.x >> 5);
    int lane = threadIdx.x & 31;
    int m = wg >> 12, n = wg & 4095;
    const float* hb = &g_h[(m * NN + n) * OUTS];
    float h0 = hb[lane], h1 = hb[lane + 32];
    float s = h0 * a1[m * 64 + lane] + h1 * a1[m * 64 + lane + 32];
    float d = h0 * a2[m * 64 + lane] + h1 * a2[m * 64 + lane + 32];
    #pragma unroll
    for (int off = 16; off; off >>= 1) {
        s += __shfl_xor_sync(0xffffffffu, s, off);
        d += __shfl_xor_sync(0xffffffffu, d, off);
    }
    if (lane == 0) { g_esrc[wg] = s; g_edst[wg] = d; }
}

// ---------------- 6) fused masked-softmax attention + PV + ELU ---------------
struct AttnSmem {
    float    hs[128][64];   // 32 KB  h tile
    float    ps[64][128];   // 32 KB  P tile
    float    ds[128];
    float    ss[64];
    unsigned adjw[256];     // 64 rows x 4 words
};

extern __shared__ char smem_raw[];

__global__ void __launch_bounds__(256) attn_k(float* __restrict__ out) {
    AttnSmem& S = *(AttnSmem*)smem_raw;
    int t = threadIdx.x, lane = t & 31, w = t >> 5;
    int m  = blockIdx.y;
    int i0 = blockIdx.x * 64;
    int r0 = w * 8;                      // warp owns 8 rows

    if (t < 64) S.ss[t] = g_esrc[m * NN + i0 + t];

    float acc[8][2];
    float den[8];
    #pragma unroll
    for (int r = 0; r < 8; ++r) { acc[r][0] = 0.f; acc[r][1] = 0.f; den[r] = 0.f; }

    for (int jt = 0; jt < NN / 128; ++jt) {
        int j0 = jt * 128;
        __syncthreads();                 // protect smem from previous iteration
        {   // load h tile [128 x 64] via float4
            const float4* hsrc = (const float4*)&g_h[(m * NN + j0) * OUTS];
            float4* hdst = (float4*)S.hs;
            #pragma unroll
            for (int k = 0; k < 8; ++k) hdst[t + 256 * k] = hsrc[t + 256 * k];
        }
        if (t < 128) S.ds[t] = g_edst[m * NN + j0 + t];
        {   // adjacency words
            int r = t >> 2, wq = t & 3;
            S.adjw[t] = g_adjbits[(i0 + r) * ADJW + (j0 >> 5) + wq];
        }
        __syncthreads();

        // phase 1: P tile (lrelu -> mask -> exp); |e| << 1 so no max-subtraction
        float* psf = &S.ps[0][0];
        #pragma unroll
        for (int k = 0; k < 32; ++k) {
            int e = t + 256 * k;
            int i = e >> 7, j = e & 127;
            float v = S.ss[i] + S.ds[j];
            v = v > 0.f ? v : LEAKF * v;
            unsigned bit = (S.adjw[i * 4 + (j >> 5)] >> (j & 31)) & 1u;
            psf[e] = bit ? __expf(v) : 0.f;
        }
        __syncthreads();

        // phase 1.5: row denominators (deterministic warp reduce)
        #pragma unroll
        for (int r = 0; r < 8; ++r) {
            const float* pr = S.ps[r0 + r];
            float sp = pr[lane] + pr[lane + 32] + pr[lane + 64] + pr[lane + 96];
            #pragma unroll
            for (int off = 16; off; off >>= 1) sp += __shfl_xor_sync(0xffffffffu, sp, off);
            den[r] += sp;
        }

        // phase 2: out += P @ H   (float4 p-loads, h reuse across 8 rows)
        #pragma unroll 4
        for (int j4 = 0; j4 < 32; ++j4) {
            int j = j4 * 4;
            float ha0 = S.hs[j    ][lane], hb0 = S.hs[j    ][lane + 32];
            float ha1 = S.hs[j + 1][lane], hb1 = S.hs[j + 1][lane + 32];
            float ha2 = S.hs[j + 2][lane], hb2 = S.hs[j + 2][lane + 32];
            float ha3 = S.hs[j + 3][lane], hb3 = S.hs[j + 3][lane + 32];
            #pragma unroll
            for (int r = 0; r < 8; ++r) {
                float4 p = *(const float4*)&S.ps[r0 + r][j];
                acc[r][0] = fmaf(p.x, ha0, fmaf(p.y, ha1, fmaf(p.z, ha2, fmaf(p.w, ha3, acc[r][0]))));
                acc[r][1] = fmaf(p.x, hb0, fmaf(p.y, hb1, fmaf(p.z, hb2, fmaf(p.w, hb3, acc[r][1]))));
            }
        }
    }

    // epilogue: normalize + ELU + store
    #pragma unroll
    for (int r = 0; r < 8; ++r) {
        int row = i0 + r0 + r;
        float inv = den[r] > 0.f ? 1.0f / den[r] : 0.f;
        float v0 = acc[r][0] * inv;
        float v1 = acc[r][1] * inv;
        v0 = v0 > 0.f ? v0 : expm1f(v0);
        v1 = v1 > 0.f ? v1 : expm1f(v1);
        out[row * (MECHS * OUTS) + m * 64 + lane]      = v0;
        out[row * (MECHS * OUTS) + m * 64 + 32 + lane] = v1;
    }
}

// ---------------- launch ------------------------------------------------------
extern "C" void kernel_launch(void* const* d_in, const int* in_sizes, int n_in,
                              void* d_out, int out_size) {
    const float* x   = (const float*)d_in[0];
    const int*   adj = (const int*)  d_in[1];
    const float* W   = (const float*)d_in[2];
    const float* a1  = (const float*)d_in[3];
    const float* a2  = (const float*)d_in[4];
    const float* Wc  = (const float*)d_in[5];
    const float* bc  = (const float*)d_in[6];
    float* out = (float*)d_out;

    cudaFuncSetAttribute(attn_k, cudaFuncAttributeMaxDynamicSharedMemorySize,
                         (int)sizeof(AttnSmem));

    pool_partial_k<<<32, 256>>>(x);
    pool_final_k<<<1, 256>>>();
    cond_k<<<2, 256>>>(Wc, bc);
    pack_adj_k<<<NN * ADJW / 8, 256>>>(adj);     // 65536 blocks, 8 words/block
    hgemm_k<<<dim3(MECHS, NN / 64), dim3(16, 16)>>>(x, W);
    esd_k<<<MECHS * NN / 8, 256>>>(a1, a2);
    attn_k<<<dim3(NN / 64, MECHS), 256, sizeof(AttnSmem)>>>(out);
}

// round 3
// speedup vs baseline: 3.0150x; 3.0150x over previous
#include <cuda_runtime.h>
#include <math.h>

#define NN    4096
#define INS   256
#define OUTS  64
#define MECHS 4
#define LEAKF 0.2f
#define ADJW  (NN/32)     // 128 words per row

// ---------------- scratch (device globals; no allocation allowed) ------------
__device__ float    g_pool_part[32][256];
__device__ float    g_pooled[256];
__device__ float    g_gb[512];                     // gamma[256], beta[256]
__device__ float    g_h[MECHS * NN * OUTS];        // FiLM'd features, 4 MB
__device__ float    g_esrc[MECHS * NN];
__device__ float    g_edst[MECHS * NN];
__device__ unsigned g_adjbits[NN * ADJW];          // packed adjacency, 2 MB

// ---------------- helpers ----------------------------------------------------
__device__ __forceinline__ unsigned f2tf32(float f) {
    unsigned u;
    asm("cvt.rna.tf32.f32 %0, %1;" : "=r"(u) : "f"(f));
    return u;
}

__device__ __forceinline__ void mma_tf32(float c[4],
                                         unsigned a0, unsigned a1, unsigned a2, unsigned a3,
                                         unsigned b0, unsigned b1) {
    asm volatile(
        "mma.sync.aligned.m16n8k8.row.col.f32.tf32.tf32.f32 "
        "{%0,%1,%2,%3}, {%4,%5,%6,%7}, {%8,%9}, {%0,%1,%2,%3};"
        : "+f"(c[0]), "+f"(c[1]), "+f"(c[2]), "+f"(c[3])
        : "r"(a0), "r"(a1), "r"(a2), "r"(a3), "r"(b0), "r"(b1));
}

// ---------------- 1) column-mean of x ----------------------------------------
__global__ void pool_partial_k(const float* __restrict__ x) {
    int t = threadIdx.x, b = blockIdx.x;
    int r0 = b * 128;
    float acc = 0.f;
    for (int r = 0; r < 128; ++r) acc += x[(r0 + r) * INS + t];
    g_pool_part[b][t] = acc;
}

__global__ void pool_final_k() {
    int t = threadIdx.x;
    float acc = 0.f;
    for (int b = 0; b < 32; ++b) acc += g_pool_part[b][t];
    g_pooled[t] = acc * (1.0f / NN);
}

// ---------------- 2) conditioner ---------------------------------------------
__global__ void cond_k(const float* __restrict__ Wc, const float* __restrict__ bc) {
    __shared__ float ps[256];
    int t = threadIdx.x;
    ps[t] = g_pooled[t];
    __syncthreads();
    int c = blockIdx.x * 256 + t;
    float acc = bc[c];
    for (int i = 0; i < INS; ++i) acc = fmaf(ps[i], Wc[i * 512 + c], acc);
    g_gb[c] = acc;
}

// ---------------- 3) pack adjacency (8 words per warp, MLP=8) ----------------
__global__ void pack_adj_k(const int* __restrict__ adj) {
    int w0   = (blockIdx.x * 8 + (threadIdx.x >> 5)) * 8;   // first word
    int lane = threadIdx.x & 31;
    const int* base = adj + w0 * 32;                         // words are linear
    int v[8];
    #pragma unroll
    for (int i = 0; i < 8; ++i) v[i] = base[i * 32 + lane];
    #pragma unroll
    for (int i = 0; i < 8; ++i) {
        unsigned msk = __ballot_sync(0xffffffffu, v[i] > 0);
        if (lane == 0) g_adjbits[w0 + i] = msk;
    }
}

// ---------------- 4) h = FiLM(x @ W[m])  (tiled SGEMM) -----------------------
__global__ void hgemm_k(const float* __restrict__ x, const float* __restrict__ W) {
    __shared__ float xs[64][20];
    __shared__ float ws[16][64];

    int m  = blockIdx.x;
    int rb = blockIdx.y * 64;
    int tx = threadIdx.x, ty = threadIdx.y;
    int t  = ty * 16 + tx;

    float acc[4][4] = {};
    const float* Wm = W + m * INS * OUTS;

    for (int k0 = 0; k0 < INS; k0 += 16) {
        {
            int r = t >> 2, kq = (t & 3) * 4;
            float4 v = *(const float4*)&x[(rb + r) * INS + k0 + kq];
            *(float4*)&xs[r][kq] = v;
        }
        {
            int kk = t >> 4, oq = (t & 15) * 4;
            *(float4*)&ws[kk][oq] = *(const float4*)&Wm[(k0 + kk) * OUTS + oq];
        }
        __syncthreads();
        #pragma unroll
        for (int k = 0; k < 16; ++k) {
            float a[4];
            #pragma unroll
            for (int i = 0; i < 4; ++i) a[i] = xs[ty * 4 + i][k];
            float4 b4 = *(const float4*)&ws[k][tx * 4];
            float b[4] = {b4.x, b4.y, b4.z, b4.w};
            #pragma unroll
            for (int i = 0; i < 4; ++i)
                #pragma unroll
                for (int j = 0; j < 4; ++j)
                    acc[i][j] = fmaf(a[i], b[j], acc[i][j]);
        }
        __syncthreads();
    }

    int oc = tx * 4;
    float4 gm = *(const float4*)&g_gb[m * 64 + oc];
    float4 bt = *(const float4*)&g_gb[256 + m * 64 + oc];
    #pragma unroll
    for (int i = 0; i < 4; ++i) {
        int row = rb + ty * 4 + i;
        float4 hv;
        hv.x = fmaf(gm.x, acc[i][0], bt.x);
        hv.y = fmaf(gm.y, acc[i][1], bt.y);
        hv.z = fmaf(gm.z, acc[i][2], bt.z);
        hv.w = fmaf(gm.w, acc[i][3], bt.w);
        *(float4*)&g_h[(m * NN + row) * OUTS + oc] = hv;
    }
}

// ---------------- 5) e_src / e_dst -------------------------------------------
__global__ void esd_k(const float* __restrict__ a1, const float* __restrict__ a2) {
    int wg   = blockIdx.x * 8 + (threadIdx.x >> 5);
    int lane = threadIdx.x & 31;
    int m = wg >> 12, n = wg & 4095;
    const float* hb = &g_h[(m * NN + n) * OUTS];
    float h0 = hb[lane], h1 = hb[lane + 32];
    float s = h0 * a1[m * 64 + lane] + h1 * a1[m * 64 + lane + 32];
    float d = h0 * a2[m * 64 + lane] + h1 * a2[m * 64 + lane + 32];
    #pragma unroll
    for (int off = 16; off; off >>= 1) {
        s += __shfl_xor_sync(0xffffffffu, s, off);
        d += __shfl_xor_sync(0xffffffffu, d, off);
    }
    if (lane == 0) { g_esrc[wg] = s; g_edst[wg] = d; }
}

// ---------------- 6) fused attention: tf32 mma.sync, on-the-fly P ------------
// Block: 128 i-rows x 1 mech, 8 warps (16 rows each). P fragments computed in
// registers (exp+mask); H tile staged in smem as tf32 with stride 72 (bank-
// conflict-free B-frag loads). Row denominators via a ones-column MMA tile.
struct AttnSmem {
    unsigned hs[128][72];   // H tile, tf32 bits, padded stride
    float    ds[128];
    unsigned adjw[512];     // 128 rows x 4 words
};

__global__ void __launch_bounds__(256) attn_k(float* __restrict__ out) {
    __shared__ AttnSmem S;

    const int t    = threadIdx.x;
    const int lane = t & 31, w = t >> 5;
    const int m    = blockIdx.y;
    const int i0   = blockIdx.x * 128;
    const int r0   = w * 16;
    const int qrow = lane >> 2;       // 0..7
    const int qcol = lane & 3;        // 0..3
    const int row1 = r0 + qrow, row2 = row1 + 8;

    const float ss1 = g_esrc[m * NN + i0 + row1];
    const float ss2 = g_esrc[m * NN + i0 + row2];
    const unsigned bones = f2tf32(qrow == 0 ? 1.0f : 0.0f);   // ones-column frag

    float c[9][4];
    #pragma unroll
    for (int n = 0; n < 9; ++n)
        #pragma unroll
        for (int q = 0; q < 4; ++q) c[n][q] = 0.f;

    const float* hbase = g_h + (size_t)m * NN * OUTS;

    for (int jt = 0; jt < NN / 128; ++jt) {
        const int j0 = jt * 128;
        __syncthreads();
        {   // H tile [128 x 64] -> tf32 smem (stride 72)
            const float4* hsrc = (const float4*)(hbase + j0 * OUTS);
            #pragma unroll
            for (int it = 0; it < 8; ++it) {
                int f = t + 256 * it;          // float4 index
                int j = f >> 4, o4 = (f & 15) * 4;
                float4 v = hsrc[f];
                uint4 u;
                u.x = f2tf32(v.x); u.y = f2tf32(v.y);
                u.z = f2tf32(v.z); u.w = f2tf32(v.w);
                *(uint4*)&S.hs[j][o4] = u;
            }
        }
        if (t < 128) S.ds[t] = g_edst[m * NN + j0 + t];
        {   // adjacency words: 512 = 128 rows x 4
            #pragma unroll
            for (int it = 0; it < 2; ++it) {
                int l = t + 256 * it;
                int r = l >> 2, wq = l & 3;
                S.adjw[l] = g_adjbits[(i0 + r) * ADJW + jt * 4 + wq];
            }
        }
        __syncthreads();

        unsigned aw1 = 0, aw2 = 0;
        #pragma unroll
        for (int ks = 0; ks < 16; ++ks) {
            if ((ks & 3) == 0) {
                aw1 = S.adjw[row1 * 4 + (ks >> 2)];
                aw2 = S.adjw[row2 * 4 + (ks >> 2)];
            }
            const int p1 = (ks & 3) * 8 + qcol;   // bit pos of j in word
            const int p2 = p1 + 4;
            const float d1 = S.ds[8 * ks + qcol];
            const float d2 = S.ds[8 * ks + qcol + 4];

            // P fragment (4 elems), lrelu = fmax(v, 0.2v); |e|<<1 so raw exp ok
            float v00 = ss1 + d1, v10 = ss2 + d1, v01 = ss1 + d2, v11 = ss2 + d2;
            v00 = fmaxf(v00, LEAKF * v00); v10 = fmaxf(v10, LEAKF * v10);
            v01 = fmaxf(v01, LEAKF * v01); v11 = fmaxf(v11, LEAKF * v11);
            float e00 = __expf(v00), e10 = __expf(v10);
            float e01 = __expf(v01), e11 = __expf(v11);
            e00 = ((aw1 >> p1) & 1u) ? e00 : 0.f;
            e10 = ((aw2 >> p1) & 1u) ? e10 : 0.f;
            e01 = ((aw1 >> p2) & 1u) ? e01 : 0.f;
            e11 = ((aw2 >> p2) & 1u) ? e11 : 0.f;
            unsigned a0 = f2tf32(e00), a1 = f2tf32(e10);
            unsigned a2 = f2tf32(e01), a3 = f2tf32(e11);

            const int kb = 8 * ks + qcol;
            #pragma unroll
            for (int nt = 0; nt < 8; ++nt) {
                unsigned b0 = S.hs[kb][nt * 8 + qrow];
                unsigned b1 = S.hs[kb + 4][nt * 8 + qrow];
                mma_tf32(c[nt], a0, a1, a2, a3, b0, b1);
            }
            mma_tf32(c[8], a0, a1, a2, a3, bones, bones);   // row-sum tile
        }
    }

    // denominators live in col 0 of tile 8 (threads with qcol==0)
    float den1 = __shfl_sync(0xffffffffu, c[8][0], lane & ~3);
    float den2 = __shfl_sync(0xffffffffu, c[8][2], lane & ~3);
    float inv1 = den1 > 0.f ? 1.0f / den1 : 0.f;
    float inv2 = den2 > 0.f ? 1.0f / den2 : 0.f;

    float* ob = out + (size_t)(i0) * (MECHS * OUTS) + m * OUTS;
    #pragma unroll
    for (int nt = 0; nt < 8; ++nt) {
        int col = nt * 8 + 2 * qcol;
        float x0 = c[nt][0] * inv1, x1 = c[nt][1] * inv1;
        float y0 = c[nt][2] * inv2, y1 = c[nt][3] * inv2;
        x0 = x0 > 0.f ? x0 : expm1f(x0);
        x1 = x1 > 0.f ? x1 : expm1f(x1);
        y0 = y0 > 0.f ? y0 : expm1f(y0);
        y1 = y1 > 0.f ? y1 : expm1f(y1);
        *(float2*)&ob[(size_t)row1 * (MECHS * OUTS) + col] = make_float2(x0, x1);
        *(float2*)&ob[(size_t)row2 * (MECHS * OUTS) + col] = make_float2(y0, y1);
    }
}

// ---------------- launch ------------------------------------------------------
extern "C" void kernel_launch(void* const* d_in, const int* in_sizes, int n_in,
                              void* d_out, int out_size) {
    const float* x   = (const float*)d_in[0];
    const int*   adj = (const int*)  d_in[1];
    const float* W   = (const float*)d_in[2];
    const float* a1  = (const float*)d_in[3];
    const float* a2  = (const float*)d_in[4];
    const float* Wc  = (const float*)d_in[5];
    const float* bc  = (const float*)d_in[6];
    float* out = (float*)d_out;

    pool_partial_k<<<32, 256>>>(x);
    pool_final_k<<<1, 256>>>();
    cond_k<<<2, 256>>>(Wc, bc);
    pack_adj_k<<<NN * ADJW / 64, 256>>>(adj);    // 8192 blocks, 64 words/block
    hgemm_k<<<dim3(MECHS, NN / 64), dim3(16, 16)>>>(x, W);
    esd_k<<<MECHS * NN / 8, 256>>>(a1, a2);
    attn_k<<<dim3(NN / 128, MECHS), 256>>>(out);
}